// round 16
// baseline (speedup 1.0000x reference)
#include <cuda_runtime.h>
#include <cuda_fp16.h>
#include <cuda_bf16.h>
#include <cstdint>

// ---------------------------------------------------------------------------
// GATConv GB300 (sm_103): N=100000, E=1600000, H=4, D=32
//   KS   setup: B fragments + w_eh + zero counters + scan sentinels
//   s1:  K3 histogram, K4 chained multi-block scan   (overlapped with K1)
//   s0:  K1 persistent 512-thread mma.sync bf16 GEMM (3-term split),
//        64-row tile, 2x8 warp grid, double-buffered A  [round-10 proven]
//   K6   edge logits (exp'd, fp16 payload) + inline CSR fill
//   K7   warp-per-node single-pass softmax + QUAD-STREAM fp16 gather-aggregate
// ---------------------------------------------------------------------------

#define N_NODES 100000
#define N_EDGES 1600000
#define NEG_SLOPE 0.2f
#define NT_TILES ((N_NODES + 63) / 64)
#define GEMM_GRID 148
#define SCAN_BLOCKS 25          // 25 * 4096 = 102400 >= N_NODES

__device__ __align__(16) __half d_feat_h[N_NODES * 128];
__device__ __align__(16) float  d_asrc[N_NODES * 4];
__device__ __align__(16) float  d_adst[N_NODES * 4];
__device__ __align__(16) uint2  d_peh[N_EDGES];   // exp'd weights as half4
__device__ __align__(16) int    d_ps[N_EDGES];
__device__ __align__(16) float  d_weh[64];        // [k=16][h=4]
__device__ __align__(16) uint4  d_Bf[8192];       // [kt8][ntg32][lane32]
__device__ __align__(16) int    d_count[N_NODES + 4];
__device__ __align__(16) int    d_count2[N_NODES];
__device__ __align__(16) int    d_offsets[N_NODES + 1];
__device__ int d_scan_val[SCAN_BLOCKS];

// ---------------- helpers ----------------
__device__ __forceinline__ uint32_t smem_to_u32(const void* p) {
    uint32_t a;
    asm("{ .reg .u64 t; cvta.to.shared.u64 t, %1; cvt.u32.u64 %0, t; }"
        : "=r"(a) : "l"(p));
    return a;
}
__device__ __forceinline__ float bfr(float x) {
    return __bfloat162float(__float2bfloat16(x));
}
__device__ __forceinline__ uint32_t pbf2(float a, float b) {
    uint16_t ua = __bfloat16_as_ushort(__float2bfloat16(a));
    uint16_t ub = __bfloat16_as_ushort(__float2bfloat16(b));
    return (uint32_t)ua | ((uint32_t)ub << 16);
}
__device__ __forceinline__ void ldsm4(uint32_t* a, uint32_t addr) {
    asm volatile("ldmatrix.sync.aligned.m8n8.x4.shared.b16 {%0,%1,%2,%3}, [%4];"
        : "=r"(a[0]), "=r"(a[1]), "=r"(a[2]), "=r"(a[3]) : "r"(addr));
}
__device__ __forceinline__ void mma_bf16(float* c, const uint32_t* a,
                                         uint32_t b0, uint32_t b1) {
    asm volatile(
        "mma.sync.aligned.m16n8k16.row.col.f32.bf16.bf16.f32 "
        "{%0,%1,%2,%3}, {%4,%5,%6,%7}, {%8,%9}, {%0,%1,%2,%3};"
        : "+f"(c[0]), "+f"(c[1]), "+f"(c[2]), "+f"(c[3])
        : "r"(a[0]), "r"(a[1]), "r"(a[2]), "r"(a[3]), "r"(b0), "r"(b1));
}

// ---------------- KS: fused setup ----------------
__global__ void k_setup(const float* __restrict__ W_fc,
                        const float* __restrict__ W_res,
                        const float* __restrict__ W_edge,
                        const float* __restrict__ attn_edge) {
    int bid = blockIdx.x, tid = threadIdx.x;
    if (bid < 32) {
        int i = bid * 256 + tid;           // 0..8191
        int lane = i & 31, ntg = (i >> 5) & 31, kt = i >> 10;
        int n = ntg * 8 + (lane >> 2);
        int kb = kt * 16 + (lane & 3) * 2;
        float w[4];
        #pragma unroll
        for (int j = 0; j < 4; j++) {
            int k = kb + (j >> 1) * 8 + (j & 1);
            w[j] = (n < 128) ? W_fc[k * 128 + n] : W_res[k * 128 + n - 128];
        }
        uint4 o;
        o.x = pbf2(w[0], w[1]);
        o.y = pbf2(w[2], w[3]);
        o.z = pbf2(w[0] - bfr(w[0]), w[1] - bfr(w[1]));
        o.w = pbf2(w[2] - bfr(w[2]), w[3] - bfr(w[3]));
        d_Bf[i] = o;
    } else {
        if (bid == 32 && tid < 64) {
            int k = tid >> 2, h = tid & 3;
            float s = 0.f;
            #pragma unroll
            for (int d = 0; d < 32; d++)
                s += W_edge[k * 128 + h * 32 + d] * attn_edge[h * 32 + d];
            d_weh[k * 4 + h] = s;
        }
        if (bid == 33 && tid < SCAN_BLOCKS) d_scan_val[tid] = -1;
        int total = (N_NODES + 4) + N_NODES;
        for (int i = (bid - 32) * 256 + tid; i < total; i += 96 * 256) {
            if (i < N_NODES + 4) d_count[i] = 0;
            else d_count2[i - (N_NODES + 4)] = 0;
        }
    }
}

// ---------------- K1: persistent 512-thread bf16x3 mma GEMM ----------------
#define SMEM_A_OFF 131072
#define GEMM_SMEM  196608

__global__ __launch_bounds__(512, 1)
void k_gemm_bf(const float* __restrict__ A, float* __restrict__ out,
               const float* __restrict__ bias,
               const float* __restrict__ attn_src,
               const float* __restrict__ attn_dst, int M) {
    extern __shared__ char sm[];
    uint32_t sb = smem_to_u32(sm);
    int tid = threadIdx.x, wid = tid >> 5, lane = tid & 31;
    int warp_m = wid & 1, warp_n = wid >> 1;   // warp_n 0..7

    // copy B fragments once (128 KB)
    {
        const uint4* g = (const uint4*)d_Bf;
        uint4* s = (uint4*)sm;
        #pragma unroll
        for (int j = 0; j < 16; j++) s[j * 512 + tid] = g[j * 512 + tid];
    }

    int r = tid >> 3, cq = tid & 7;        // A fill: 16 floats per thread
    float4 a_st[4];

    auto load_regs = [&](int tile) {
        int grow = tile * 64 + r;
        if (grow < M) {
            const float4* ap = (const float4*)(A + (size_t)grow * 128 + cq * 16);
            #pragma unroll
            for (int q = 0; q < 4; q++) a_st[q] = __ldg(ap + q);
        } else {
            #pragma unroll
            for (int q = 0; q < 4; q++) a_st[q] = make_float4(0.f, 0.f, 0.f, 0.f);
        }
    };
    auto store_stage = [&](int buf) {
        char* hb = sm + SMEM_A_OFF + (buf * 2 + 0) * 16384 + r * 256;
        char* lb = sm + SMEM_A_OFF + (buf * 2 + 1) * 16384 + r * 256;
        int sw = r & 7;
        #pragma unroll
        for (int cc = 0; cc < 2; cc++) {
            float xs[8] = {a_st[cc*2].x, a_st[cc*2].y, a_st[cc*2].z, a_st[cc*2].w,
                           a_st[cc*2+1].x, a_st[cc*2+1].y, a_st[cc*2+1].z, a_st[cc*2+1].w};
            uint32_t hw[4], lw[4];
            #pragma unroll
            for (int p = 0; p < 4; p++) {
                float x0 = xs[p*2], x1 = xs[p*2+1];
                float h0 = bfr(x0), h1 = bfr(x1);
                hw[p] = pbf2(x0, x1);
                lw[p] = pbf2(x0 - h0, x1 - h1);
            }
            int phys = (cq * 2 + cc) ^ sw;
            *(uint4*)(hb + phys * 16) = make_uint4(hw[0], hw[1], hw[2], hw[3]);
            *(uint4*)(lb + phys * 16) = make_uint4(lw[0], lw[1], lw[2], lw[3]);
        }
    };

    const uint4* B4 = (const uint4*)sm;
    int rl = lane & 15, cl = lane >> 4;
    int lr = lane >> 2, lc = (lane & 3) * 2;

    int tile = blockIdx.x;
    if (tile < NT_TILES) load_regs(tile);
    store_stage(0);
    __syncthreads();
    int buf = 0;

    for (; tile < NT_TILES; tile += GEMM_GRID) {
        int nxt = tile + GEMM_GRID;
        bool hn = nxt < NT_TILES;
        if (hn) load_regs(nxt);

        float acc[2][4][4];
        #pragma unroll
        for (int a = 0; a < 2; a++)
            #pragma unroll
            for (int b = 0; b < 4; b++)
                #pragma unroll
                for (int q = 0; q < 4; q++) acc[a][b][q] = 0.f;

        uint32_t aH = sb + SMEM_A_OFF + (buf * 2) * 16384;
        uint32_t aL = aH + 16384;

        #pragma unroll
        for (int kt = 0; kt < 8; kt++) {
            uint32_t ah[2][4], al[2][4];
            #pragma unroll
            for (int mt = 0; mt < 2; mt++) {
                int rr = warp_m * 32 + mt * 16 + rl;
                int c = kt * 2 + cl;
                uint32_t off = (uint32_t)(rr * 256 + ((c ^ (rr & 7)) << 4));
                ldsm4(ah[mt], aH + off);
                ldsm4(al[mt], aL + off);
            }
            #pragma unroll
            for (int nt = 0; nt < 4; nt++) {
                uint4 b = B4[(kt * 32 + warp_n * 4 + nt) * 32 + lane];
                #pragma unroll
                for (int mt = 0; mt < 2; mt++) {
                    mma_bf16(acc[mt][nt], ah[mt], b.x, b.y);
                    mma_bf16(acc[mt][nt], al[mt], b.x, b.y);
                    mma_bf16(acc[mt][nt], ah[mt], b.z, b.w);
                }
            }
        }

        if (hn) store_stage(buf ^ 1);

        // ---- epilogue
        int row0 = tile * 64;
        bool is_feat = (warp_n < 4);
        #pragma unroll
        for (int mt = 0; mt < 2; mt++) {
            int r0g = row0 + warp_m * 32 + mt * 16 + lr;
            #pragma unroll
            for (int nt = 0; nt < 4; nt++) {
                int col = warp_n * 32 + nt * 8 + lc;
                float* c = acc[mt][nt];
                if (is_feat) {
                    if (r0g < M)
                        *(__half2*)(d_feat_h + (size_t)r0g * 128 + col) =
                            __floats2half2_rn(c[0], c[1]);
                    if (r0g + 8 < M)
                        *(__half2*)(d_feat_h + (size_t)(r0g + 8) * 128 + col) =
                            __floats2half2_rn(c[2], c[3]);
                } else {
                    int oc = col - 128;
                    float2 bz = *(const float2*)(bias + oc);
                    if (r0g < M)
                        *(float2*)(out + (size_t)r0g * 128 + oc) =
                            make_float2(c[0] + bz.x, c[1] + bz.y);
                    if (r0g + 8 < M)
                        *(float2*)(out + (size_t)(r0g + 8) * 128 + oc) =
                            make_float2(c[2] + bz.x, c[3] + bz.y);
                }
            }
            if (is_feat) {
                int head = warp_n;
                float ps0 = 0.f, ps1 = 0.f, pd0 = 0.f, pd1 = 0.f;
                #pragma unroll
                for (int nt = 0; nt < 4; nt++) {
                    int cih = nt * 8 + lc;
                    float s0 = __ldg(attn_src + head * 32 + cih);
                    float s1 = __ldg(attn_src + head * 32 + cih + 1);
                    float e0 = __ldg(attn_dst + head * 32 + cih);
                    float e1 = __ldg(attn_dst + head * 32 + cih + 1);
                    float* c = acc[mt][nt];
                    ps0 += c[0] * s0 + c[1] * s1;
                    ps1 += c[2] * s0 + c[3] * s1;
                    pd0 += c[0] * e0 + c[1] * e1;
                    pd1 += c[2] * e0 + c[3] * e1;
                }
                #pragma unroll
                for (int o = 1; o < 4; o <<= 1) {
                    ps0 += __shfl_xor_sync(0xffffffffu, ps0, o);
                    ps1 += __shfl_xor_sync(0xffffffffu, ps1, o);
                    pd0 += __shfl_xor_sync(0xffffffffu, pd0, o);
                    pd1 += __shfl_xor_sync(0xffffffffu, pd1, o);
                }
                if ((lane & 3) == 0) {
                    if (r0g < M) {
                        d_asrc[r0g * 4 + head] = ps0;
                        d_adst[r0g * 4 + head] = pd0;
                    }
                    if (r0g + 8 < M) {
                        d_asrc[(r0g + 8) * 4 + head] = ps1;
                        d_adst[(r0g + 8) * 4 + head] = pd1;
                    }
                }
            }
        }
        __syncthreads();
        buf ^= 1;
    }
}

// ---------------- K3: histogram ----------------
__global__ void k_hist(const int* __restrict__ dst) {
    int i4 = (blockIdx.x * blockDim.x + threadIdx.x) * 4;
    if (i4 + 3 < N_EDGES) {
        int4 d = *(const int4*)(dst + i4);
        atomicAdd(&d_count[d.x], 1);
        atomicAdd(&d_count[d.y], 1);
        atomicAdd(&d_count[d.z], 1);
        atomicAdd(&d_count[d.w], 1);
    } else {
        for (int i = i4; i < N_EDGES; i++) atomicAdd(&d_count[dst[i]], 1);
    }
}

// ---------------- K4: chained multi-block exclusive scan -------------------
__global__ __launch_bounds__(1024, 1)
void k_scan_mb() {
    __shared__ int wsum[32];
    __shared__ int s_prefix;
    int bid = blockIdx.x, tid = threadIdx.x;
    int lane = tid & 31, wid = tid >> 5;

    int i0 = bid * 4096 + tid * 4;
    int v0 = 0, v1 = 0, v2 = 0, v3 = 0;
    if (i0 + 3 < N_NODES) {
        int4 v = *(const int4*)&d_count[i0];
        v0 = v.x; v1 = v.y; v2 = v.z; v3 = v.w;
    } else {
        if (i0 + 0 < N_NODES) v0 = d_count[i0 + 0];
        if (i0 + 1 < N_NODES) v1 = d_count[i0 + 1];
        if (i0 + 2 < N_NODES) v2 = d_count[i0 + 2];
        if (i0 + 3 < N_NODES) v3 = d_count[i0 + 3];
    }
    int p0 = v0, p1 = p0 + v1, p2 = p1 + v2, p3 = p2 + v3;
    int x = p3;
    #pragma unroll
    for (int o = 1; o < 32; o <<= 1) {
        int t = __shfl_up_sync(0xffffffffu, x, o);
        if (lane >= o) x += t;
    }
    if (lane == 31) wsum[wid] = x;
    __syncthreads();
    if (wid == 0) {
        int y = wsum[lane];
        #pragma unroll
        for (int o = 1; o < 32; o <<= 1) {
            int t = __shfl_up_sync(0xffffffffu, y, o);
            if (lane >= o) y += t;
        }
        wsum[lane] = y;
    }
    __syncthreads();
    int warpoff = (wid > 0) ? wsum[wid - 1] : 0;
    int texcl = x - p3;
    int block_total = wsum[31];

    if (tid == 0) {
        int prefix = 0;
        if (bid > 0) {
            while ((prefix = atomicAdd(&d_scan_val[bid - 1], 0)) == -1) {}
        }
        atomicExch(&d_scan_val[bid], prefix + block_total);
        s_prefix = prefix;
        if (bid == 0) d_offsets[0] = 0;
    }
    __syncthreads();
    int bs = s_prefix + warpoff + texcl;

    if (i0 + 0 < N_NODES) d_offsets[i0 + 1] = bs + p0;
    if (i0 + 1 < N_NODES) d_offsets[i0 + 2] = bs + p1;
    if (i0 + 2 < N_NODES) d_offsets[i0 + 3] = bs + p2;
    if (i0 + 3 < N_NODES) d_offsets[i0 + 4] = bs + p3;
}

// ---------------- K6: edge logits (exp'd fp16) + inline CSR fill ------------
__global__ void k_edge_e(const float* __restrict__ edge_inputs,
                         const int* __restrict__ src,
                         const int* __restrict__ dst) {
    __shared__ float sweh[64];
    if (threadIdx.x < 64) sweh[threadIdx.x] = d_weh[threadIdx.x];
    __syncthreads();

    int e = blockIdx.x * blockDim.x + threadIdx.x;
    if (e >= N_EDGES) return;

    int s = src[e];
    int d = dst[e];
    float4 as = *(const float4*)(d_asrc + s * 4);
    float4 ad = *(const float4*)(d_adst + d * 4);

    float ae[4] = {0.f, 0.f, 0.f, 0.f};
    const float* ep = edge_inputs + (size_t)e * 16;
    #pragma unroll
    for (int kq = 0; kq < 4; kq++) {
        float4 ev = *(const float4*)(ep + kq * 4);
        float efs[4] = {ev.x, ev.y, ev.z, ev.w};
        #pragma unroll
        for (int kk = 0; kk < 4; kk++) {
            int k = kq * 4 + kk;
            #pragma unroll
            for (int h = 0; h < 4; h++) ae[h] += efs[kk] * sweh[k * 4 + h];
        }
    }

    float av[4] = {as.x, as.y, as.z, as.w};
    float dv[4] = {ad.x, ad.y, ad.z, ad.w};
    float res[4];
    #pragma unroll
    for (int h = 0; h < 4; h++) {
        float v = av[h] + dv[h] + ae[h];
        float t = (v > 0.f) ? v : NEG_SLOPE * v;
        res[h] = __expf(t);
    }

    int p = d_offsets[d] + atomicAdd(&d_count2[d], 1);
    __half2 h01 = __floats2half2_rn(res[0], res[1]);
    __half2 h23 = __floats2half2_rn(res[2], res[3]);
    d_peh[p] = make_uint2(*(uint32_t*)&h01, *(uint32_t*)&h23);
    d_ps[p] = s;
}

// ---------------- K7: warp-per-node softmax + QUAD-STREAM aggregate --------
__device__ __forceinline__ void agg_one(int k, int hl, int lane,
                                        uint32_t pvx, uint32_t pvy, int sn,
                                        float* a0, float* a1, float* a2, float* a3) {
    uint32_t px = __shfl_sync(0xffffffffu, pvx, k);
    uint32_t py = __shfl_sync(0xffffffffu, pvy, k);
    int snk = __shfl_sync(0xffffffffu, sn, k);
    uint32_t sel = (hl < 2) ? px : py;
    float2 wf = __half22float2(*(__half2*)&sel);
    float w = (hl & 1) ? wf.y : wf.x;
    uint2 hv = *(const uint2*)(d_feat_h + (size_t)snk * 128 + lane * 4);
    float2 f0 = __half22float2(*(__half2*)&hv.x);
    float2 f1 = __half22float2(*(__half2*)&hv.y);
    *a0 += f0.x * w; *a1 += f0.y * w;
    *a2 += f1.x * w; *a3 += f1.y * w;
}

__global__ void k_aggregate(float* __restrict__ out) {
    int warp = (blockIdx.x * blockDim.x + threadIdx.x) >> 5;
    int lane = threadIdx.x & 31;
    if (warp >= N_NODES) return;
    int n = warp;

    int begin = d_offsets[n];
    int deg = d_offsets[n + 1] - begin;
    if (deg == 0) return;

    int hl = lane >> 3;
    float s0 = 0.f, s1 = 0.f, s2 = 0.f, s3 = 0.f;
    // 4 independent accumulator sets
    float A[4] = {0.f, 0.f, 0.f, 0.f};
    float B[4] = {0.f, 0.f, 0.f, 0.f};
    float C[4] = {0.f, 0.f, 0.f, 0.f};
    float D[4] = {0.f, 0.f, 0.f, 0.f};

    for (int b = 0; b < deg; b += 32) {
        int j = b + lane;
        uint2 pv = make_uint2(0u, 0u);
        int sn = 0;
        if (j < deg) {
            pv = d_peh[begin + j];
            sn = d_ps[begin + j];
        }
        float2 f01 = __half22float2(*(__half2*)&pv.x);
        float2 f23 = __half22float2(*(__half2*)&pv.y);
        s0 += f01.x; s1 += f01.y; s2 += f23.x; s3 += f23.y;

        int cnt = min(32, deg - b);
        int q = cnt >> 2;
        #pragma unroll 2
        for (int k = 0; k < q; k++) {
            agg_one(k,         hl, lane, pv.x, pv.y, sn, &A[0], &A[1], &A[2], &A[3]);
            agg_one(k + q,     hl, lane, pv.x, pv.y, sn, &B[0], &B[1], &B[2], &B[3]);
            agg_one(k + 2 * q, hl, lane, pv.x, pv.y, sn, &C[0], &C[1], &C[2], &C[3]);
            agg_one(k + 3 * q, hl, lane, pv.x, pv.y, sn, &D[0], &D[1], &D[2], &D[3]);
        }
        for (int k = 4 * q; k < cnt; k++)
            agg_one(k, hl, lane, pv.x, pv.y, sn, &A[0], &A[1], &A[2], &A[3]);
    }
    float acc0 = (A[0] + B[0]) + (C[0] + D[0]);
    float acc1 = (A[1] + B[1]) + (C[1] + D[1]);
    float acc2 = (A[2] + B[2]) + (C[2] + D[2]);
    float acc3 = (A[3] + B[3]) + (C[3] + D[3]);

    #pragma unroll
    for (int o = 16; o > 0; o >>= 1) {
        s0 += __shfl_xor_sync(0xffffffffu, s0, o);
        s1 += __shfl_xor_sync(0xffffffffu, s1, o);
        s2 += __shfl_xor_sync(0xffffffffu, s2, o);
        s3 += __shfl_xor_sync(0xffffffffu, s3, o);
    }
    float s = (hl < 2) ? (hl == 0 ? s0 : s1) : (hl == 2 ? s2 : s3);
    float inv = 1.f / s;

    float4* op = (float4*)(out + (size_t)n * 128 + lane * 4);
    float4 ov = *op;  // residual + bias from GEMM epilogue
    ov.x += acc0 * inv; ov.y += acc1 * inv;
    ov.z += acc2 * inv; ov.w += acc3 * inv;
    *op = ov;
}

// ---------------------------------------------------------------------------
extern "C" void kernel_launch(void* const* d_in, const int* in_sizes, int n_in,
                              void* d_out, int out_size) {
    const float* node_inputs = (const float*)d_in[0];
    const float* edge_inputs = (const float*)d_in[1];
    const int*   src         = (const int*)d_in[2];
    const int*   dst         = (const int*)d_in[3];
    const float* W_fc        = (const float*)d_in[4];
    const float* attn_src_p  = (const float*)d_in[5];
    const float* attn_dst_p  = (const float*)d_in[6];
    const float* W_edge      = (const float*)d_in[7];
    const float* attn_edge_p = (const float*)d_in[8];
    const float* W_res       = (const float*)d_in[9];
    const float* bias_p      = (const float*)d_in[10];
    float* out = (float*)d_out;

    static cudaStream_t s1;
    static cudaEvent_t evA, evS;
    static bool inited = false;
    if (!inited) {
        cudaStreamCreateWithFlags(&s1, cudaStreamNonBlocking);
        cudaEventCreateWithFlags(&evA, cudaEventDisableTiming);
        cudaEventCreateWithFlags(&evS, cudaEventDisableTiming);
        cudaFuncSetAttribute(k_gemm_bf,
                             cudaFuncAttributeMaxDynamicSharedMemorySize,
                             GEMM_SMEM);
        inited = true;
    }

    // setup on default stream
    k_setup<<<128, 256>>>(W_fc, W_res, W_edge, attn_edge_p);
    cudaEventRecord(evA, 0);

    // side stream: histogram + scan (independent of GEMM)
    cudaStreamWaitEvent(s1, evA, 0);
    k_hist<<<(N_EDGES / 4 + 255) / 256, 256, 0, s1>>>(dst);
    k_scan_mb<<<SCAN_BLOCKS, 1024, 0, s1>>>();
    cudaEventRecord(evS, s1);

    // main stream: GEMM overlapping with hist/scan
    k_gemm_bf<<<GEMM_GRID, 512, GEMM_SMEM>>>(
        node_inputs, out, bias_p, attn_src_p, attn_dst_p, N_NODES);

    // join, then edge + aggregate
    cudaStreamWaitEvent(0, evS, 0);
    k_edge_e<<<(N_EDGES + 255) / 256, 256>>>(edge_inputs, src, dst);
    k_aggregate<<<(N_NODES * 32 + 255) / 256, 256>>>(out);
}

// round 17
// speedup vs baseline: 1.1027x; 1.1027x over previous
#include <cuda_runtime.h>
#include <cuda_fp16.h>
#include <cuda_bf16.h>
#include <cstdint>

// ---------------------------------------------------------------------------
// GATConv GB300 (sm_103): N=100000, E=1600000, H=4, D=32
//   KS   setup: B fragments + w_eh + zero counters + scan sentinels
//   s1:  K3 histogram, K4 chained multi-block scan   (overlapped with K1)
//   s0:  K1 persistent 512-thread mma.sync bf16 GEMM (3-term split),
//        64-row tile, 2x8 warp grid, double-buffered A  [round-10 proven]
//   K6   edge logits (exp'd, fp16) + inline CSR fill -> fused 16B payload
//   K7   warp-per-node single-pass softmax + DUAL-STREAM fp16 gather-aggregate
// ---------------------------------------------------------------------------

#define N_NODES 100000
#define N_EDGES 1600000
#define NEG_SLOPE 0.2f
#define NT_TILES ((N_NODES + 63) / 64)
#define GEMM_GRID 148
#define SCAN_BLOCKS 25          // 25 * 4096 = 102400 >= N_NODES

__device__ __align__(16) __half d_feat_h[N_NODES * 128];
__device__ __align__(16) float  d_asrc[N_NODES * 4];
__device__ __align__(16) float  d_adst[N_NODES * 4];
__device__ __align__(16) uint4  d_pay[N_EDGES];   // {w01, w23, src, pad}
__device__ __align__(16) float  d_weh[64];        // [k=16][h=4]
__device__ __align__(16) uint4  d_Bf[8192];       // [kt8][ntg32][lane32]
__device__ __align__(16) int    d_count[N_NODES + 4];
__device__ __align__(16) int    d_count2[N_NODES];
__device__ __align__(16) int    d_offsets[N_NODES + 1];
__device__ int d_scan_val[SCAN_BLOCKS];

// ---------------- helpers ----------------
__device__ __forceinline__ uint32_t smem_to_u32(const void* p) {
    uint32_t a;
    asm("{ .reg .u64 t; cvta.to.shared.u64 t, %1; cvt.u32.u64 %0, t; }"
        : "=r"(a) : "l"(p));
    return a;
}
__device__ __forceinline__ float bfr(float x) {
    return __bfloat162float(__float2bfloat16(x));
}
__device__ __forceinline__ uint32_t pbf2(float a, float b) {
    uint16_t ua = __bfloat16_as_ushort(__float2bfloat16(a));
    uint16_t ub = __bfloat16_as_ushort(__float2bfloat16(b));
    return (uint32_t)ua | ((uint32_t)ub << 16);
}
__device__ __forceinline__ void ldsm4(uint32_t* a, uint32_t addr) {
    asm volatile("ldmatrix.sync.aligned.m8n8.x4.shared.b16 {%0,%1,%2,%3}, [%4];"
        : "=r"(a[0]), "=r"(a[1]), "=r"(a[2]), "=r"(a[3]) : "r"(addr));
}
__device__ __forceinline__ void mma_bf16(float* c, const uint32_t* a,
                                         uint32_t b0, uint32_t b1) {
    asm volatile(
        "mma.sync.aligned.m16n8k16.row.col.f32.bf16.bf16.f32 "
        "{%0,%1,%2,%3}, {%4,%5,%6,%7}, {%8,%9}, {%0,%1,%2,%3};"
        : "+f"(c[0]), "+f"(c[1]), "+f"(c[2]), "+f"(c[3])
        : "r"(a[0]), "r"(a[1]), "r"(a[2]), "r"(a[3]), "r"(b0), "r"(b1));
}

// ---------------- KS: fused setup ----------------
__global__ void k_setup(const float* __restrict__ W_fc,
                        const float* __restrict__ W_res,
                        const float* __restrict__ W_edge,
                        const float* __restrict__ attn_edge) {
    int bid = blockIdx.x, tid = threadIdx.x;
    if (bid < 32) {
        int i = bid * 256 + tid;           // 0..8191
        int lane = i & 31, ntg = (i >> 5) & 31, kt = i >> 10;
        int n = ntg * 8 + (lane >> 2);
        int kb = kt * 16 + (lane & 3) * 2;
        float w[4];
        #pragma unroll
        for (int j = 0; j < 4; j++) {
            int k = kb + (j >> 1) * 8 + (j & 1);
            w[j] = (n < 128) ? W_fc[k * 128 + n] : W_res[k * 128 + n - 128];
        }
        uint4 o;
        o.x = pbf2(w[0], w[1]);
        o.y = pbf2(w[2], w[3]);
        o.z = pbf2(w[0] - bfr(w[0]), w[1] - bfr(w[1]));
        o.w = pbf2(w[2] - bfr(w[2]), w[3] - bfr(w[3]));
        d_Bf[i] = o;
    } else {
        if (bid == 32 && tid < 64) {
            int k = tid >> 2, h = tid & 3;
            float s = 0.f;
            #pragma unroll
            for (int d = 0; d < 32; d++)
                s += W_edge[k * 128 + h * 32 + d] * attn_edge[h * 32 + d];
            d_weh[k * 4 + h] = s;
        }
        if (bid == 33 && tid < SCAN_BLOCKS) d_scan_val[tid] = -1;
        int total = (N_NODES + 4) + N_NODES;
        for (int i = (bid - 32) * 256 + tid; i < total; i += 96 * 256) {
            if (i < N_NODES + 4) d_count[i] = 0;
            else d_count2[i - (N_NODES + 4)] = 0;
        }
    }
}

// ---------------- K1: persistent 512-thread bf16x3 mma GEMM ----------------
#define SMEM_A_OFF 131072
#define GEMM_SMEM  196608

__global__ __launch_bounds__(512, 1)
void k_gemm_bf(const float* __restrict__ A, float* __restrict__ out,
               const float* __restrict__ bias,
               const float* __restrict__ attn_src,
               const float* __restrict__ attn_dst, int M) {
    extern __shared__ char sm[];
    uint32_t sb = smem_to_u32(sm);
    int tid = threadIdx.x, wid = tid >> 5, lane = tid & 31;
    int warp_m = wid & 1, warp_n = wid >> 1;   // warp_n 0..7

    // copy B fragments once (128 KB)
    {
        const uint4* g = (const uint4*)d_Bf;
        uint4* s = (uint4*)sm;
        #pragma unroll
        for (int j = 0; j < 16; j++) s[j * 512 + tid] = g[j * 512 + tid];
    }

    int r = tid >> 3, cq = tid & 7;        // A fill: 16 floats per thread
    float4 a_st[4];

    auto load_regs = [&](int tile) {
        int grow = tile * 64 + r;
        if (grow < M) {
            const float4* ap = (const float4*)(A + (size_t)grow * 128 + cq * 16);
            #pragma unroll
            for (int q = 0; q < 4; q++) a_st[q] = __ldg(ap + q);
        } else {
            #pragma unroll
            for (int q = 0; q < 4; q++) a_st[q] = make_float4(0.f, 0.f, 0.f, 0.f);
        }
    };
    auto store_stage = [&](int buf) {
        char* hb = sm + SMEM_A_OFF + (buf * 2 + 0) * 16384 + r * 256;
        char* lb = sm + SMEM_A_OFF + (buf * 2 + 1) * 16384 + r * 256;
        int sw = r & 7;
        #pragma unroll
        for (int cc = 0; cc < 2; cc++) {
            float xs[8] = {a_st[cc*2].x, a_st[cc*2].y, a_st[cc*2].z, a_st[cc*2].w,
                           a_st[cc*2+1].x, a_st[cc*2+1].y, a_st[cc*2+1].z, a_st[cc*2+1].w};
            uint32_t hw[4], lw[4];
            #pragma unroll
            for (int p = 0; p < 4; p++) {
                float x0 = xs[p*2], x1 = xs[p*2+1];
                float h0 = bfr(x0), h1 = bfr(x1);
                hw[p] = pbf2(x0, x1);
                lw[p] = pbf2(x0 - h0, x1 - h1);
            }
            int phys = (cq * 2 + cc) ^ sw;
            *(uint4*)(hb + phys * 16) = make_uint4(hw[0], hw[1], hw[2], hw[3]);
            *(uint4*)(lb + phys * 16) = make_uint4(lw[0], lw[1], lw[2], lw[3]);
        }
    };

    const uint4* B4 = (const uint4*)sm;
    int rl = lane & 15, cl = lane >> 4;
    int lr = lane >> 2, lc = (lane & 3) * 2;

    int tile = blockIdx.x;
    if (tile < NT_TILES) load_regs(tile);
    store_stage(0);
    __syncthreads();
    int buf = 0;

    for (; tile < NT_TILES; tile += GEMM_GRID) {
        int nxt = tile + GEMM_GRID;
        bool hn = nxt < NT_TILES;
        if (hn) load_regs(nxt);

        float acc[2][4][4];
        #pragma unroll
        for (int a = 0; a < 2; a++)
            #pragma unroll
            for (int b = 0; b < 4; b++)
                #pragma unroll
                for (int q = 0; q < 4; q++) acc[a][b][q] = 0.f;

        uint32_t aH = sb + SMEM_A_OFF + (buf * 2) * 16384;
        uint32_t aL = aH + 16384;

        #pragma unroll
        for (int kt = 0; kt < 8; kt++) {
            uint32_t ah[2][4], al[2][4];
            #pragma unroll
            for (int mt = 0; mt < 2; mt++) {
                int rr = warp_m * 32 + mt * 16 + rl;
                int c = kt * 2 + cl;
                uint32_t off = (uint32_t)(rr * 256 + ((c ^ (rr & 7)) << 4));
                ldsm4(ah[mt], aH + off);
                ldsm4(al[mt], aL + off);
            }
            #pragma unroll
            for (int nt = 0; nt < 4; nt++) {
                uint4 b = B4[(kt * 32 + warp_n * 4 + nt) * 32 + lane];
                #pragma unroll
                for (int mt = 0; mt < 2; mt++) {
                    mma_bf16(acc[mt][nt], ah[mt], b.x, b.y);
                    mma_bf16(acc[mt][nt], al[mt], b.x, b.y);
                    mma_bf16(acc[mt][nt], ah[mt], b.z, b.w);
                }
            }
        }

        if (hn) store_stage(buf ^ 1);

        // ---- epilogue
        int row0 = tile * 64;
        bool is_feat = (warp_n < 4);
        #pragma unroll
        for (int mt = 0; mt < 2; mt++) {
            int r0g = row0 + warp_m * 32 + mt * 16 + lr;
            #pragma unroll
            for (int nt = 0; nt < 4; nt++) {
                int col = warp_n * 32 + nt * 8 + lc;
                float* c = acc[mt][nt];
                if (is_feat) {
                    if (r0g < M)
                        *(__half2*)(d_feat_h + (size_t)r0g * 128 + col) =
                            __floats2half2_rn(c[0], c[1]);
                    if (r0g + 8 < M)
                        *(__half2*)(d_feat_h + (size_t)(r0g + 8) * 128 + col) =
                            __floats2half2_rn(c[2], c[3]);
                } else {
                    int oc = col - 128;
                    float2 bz = *(const float2*)(bias + oc);
                    if (r0g < M)
                        *(float2*)(out + (size_t)r0g * 128 + oc) =
                            make_float2(c[0] + bz.x, c[1] + bz.y);
                    if (r0g + 8 < M)
                        *(float2*)(out + (size_t)(r0g + 8) * 128 + oc) =
                            make_float2(c[2] + bz.x, c[3] + bz.y);
                }
            }
            if (is_feat) {
                int head = warp_n;
                float ps0 = 0.f, ps1 = 0.f, pd0 = 0.f, pd1 = 0.f;
                #pragma unroll
                for (int nt = 0; nt < 4; nt++) {
                    int cih = nt * 8 + lc;
                    float s0 = __ldg(attn_src + head * 32 + cih);
                    float s1 = __ldg(attn_src + head * 32 + cih + 1);
                    float e0 = __ldg(attn_dst + head * 32 + cih);
                    float e1 = __ldg(attn_dst + head * 32 + cih + 1);
                    float* c = acc[mt][nt];
                    ps0 += c[0] * s0 + c[1] * s1;
                    ps1 += c[2] * s0 + c[3] * s1;
                    pd0 += c[0] * e0 + c[1] * e1;
                    pd1 += c[2] * e0 + c[3] * e1;
                }
                #pragma unroll
                for (int o = 1; o < 4; o <<= 1) {
                    ps0 += __shfl_xor_sync(0xffffffffu, ps0, o);
                    ps1 += __shfl_xor_sync(0xffffffffu, ps1, o);
                    pd0 += __shfl_xor_sync(0xffffffffu, pd0, o);
                    pd1 += __shfl_xor_sync(0xffffffffu, pd1, o);
                }
                if ((lane & 3) == 0) {
                    if (r0g < M) {
                        d_asrc[r0g * 4 + head] = ps0;
                        d_adst[r0g * 4 + head] = pd0;
                    }
                    if (r0g + 8 < M) {
                        d_asrc[(r0g + 8) * 4 + head] = ps1;
                        d_adst[(r0g + 8) * 4 + head] = pd1;
                    }
                }
            }
        }
        __syncthreads();
        buf ^= 1;
    }
}

// ---------------- K3: histogram ----------------
__global__ void k_hist(const int* __restrict__ dst) {
    int i4 = (blockIdx.x * blockDim.x + threadIdx.x) * 4;
    if (i4 + 3 < N_EDGES) {
        int4 d = *(const int4*)(dst + i4);
        atomicAdd(&d_count[d.x], 1);
        atomicAdd(&d_count[d.y], 1);
        atomicAdd(&d_count[d.z], 1);
        atomicAdd(&d_count[d.w], 1);
    } else {
        for (int i = i4; i < N_EDGES; i++) atomicAdd(&d_count[dst[i]], 1);
    }
}

// ---------------- K4: chained multi-block exclusive scan -------------------
__global__ __launch_bounds__(1024, 1)
void k_scan_mb() {
    __shared__ int wsum[32];
    __shared__ int s_prefix;
    int bid = blockIdx.x, tid = threadIdx.x;
    int lane = tid & 31, wid = tid >> 5;

    int i0 = bid * 4096 + tid * 4;
    int v0 = 0, v1 = 0, v2 = 0, v3 = 0;
    if (i0 + 3 < N_NODES) {
        int4 v = *(const int4*)&d_count[i0];
        v0 = v.x; v1 = v.y; v2 = v.z; v3 = v.w;
    } else {
        if (i0 + 0 < N_NODES) v0 = d_count[i0 + 0];
        if (i0 + 1 < N_NODES) v1 = d_count[i0 + 1];
        if (i0 + 2 < N_NODES) v2 = d_count[i0 + 2];
        if (i0 + 3 < N_NODES) v3 = d_count[i0 + 3];
    }
    int p0 = v0, p1 = p0 + v1, p2 = p1 + v2, p3 = p2 + v3;
    int x = p3;
    #pragma unroll
    for (int o = 1; o < 32; o <<= 1) {
        int t = __shfl_up_sync(0xffffffffu, x, o);
        if (lane >= o) x += t;
    }
    if (lane == 31) wsum[wid] = x;
    __syncthreads();
    if (wid == 0) {
        int y = wsum[lane];
        #pragma unroll
        for (int o = 1; o < 32; o <<= 1) {
            int t = __shfl_up_sync(0xffffffffu, y, o);
            if (lane >= o) y += t;
        }
        wsum[lane] = y;
    }
    __syncthreads();
    int warpoff = (wid > 0) ? wsum[wid - 1] : 0;
    int texcl = x - p3;
    int block_total = wsum[31];

    if (tid == 0) {
        int prefix = 0;
        if (bid > 0) {
            while ((prefix = atomicAdd(&d_scan_val[bid - 1], 0)) == -1) {}
        }
        atomicExch(&d_scan_val[bid], prefix + block_total);
        s_prefix = prefix;
        if (bid == 0) d_offsets[0] = 0;
    }
    __syncthreads();
    int bs = s_prefix + warpoff + texcl;

    if (i0 + 0 < N_NODES) d_offsets[i0 + 1] = bs + p0;
    if (i0 + 1 < N_NODES) d_offsets[i0 + 2] = bs + p1;
    if (i0 + 2 < N_NODES) d_offsets[i0 + 3] = bs + p2;
    if (i0 + 3 < N_NODES) d_offsets[i0 + 4] = bs + p3;
}

// ---------------- K6: edge logits (exp'd fp16) + fused 16B payload ----------
__global__ void k_edge_e(const float* __restrict__ edge_inputs,
                         const int* __restrict__ src,
                         const int* __restrict__ dst) {
    __shared__ float sweh[64];
    if (threadIdx.x < 64) sweh[threadIdx.x] = d_weh[threadIdx.x];
    __syncthreads();

    int e = blockIdx.x * blockDim.x + threadIdx.x;
    if (e >= N_EDGES) return;

    int s = src[e];
    int d = dst[e];
    float4 as = *(const float4*)(d_asrc + s * 4);
    float4 ad = *(const float4*)(d_adst + d * 4);

    float ae[4] = {0.f, 0.f, 0.f, 0.f};
    const float* ep = edge_inputs + (size_t)e * 16;
    #pragma unroll
    for (int kq = 0; kq < 4; kq++) {
        float4 ev = *(const float4*)(ep + kq * 4);
        float efs[4] = {ev.x, ev.y, ev.z, ev.w};
        #pragma unroll
        for (int kk = 0; kk < 4; kk++) {
            int k = kq * 4 + kk;
            #pragma unroll
            for (int h = 0; h < 4; h++) ae[h] += efs[kk] * sweh[k * 4 + h];
        }
    }

    float av[4] = {as.x, as.y, as.z, as.w};
    float dv[4] = {ad.x, ad.y, ad.z, ad.w};
    float res[4];
    #pragma unroll
    for (int h = 0; h < 4; h++) {
        float v = av[h] + dv[h] + ae[h];
        float t = (v > 0.f) ? v : NEG_SLOPE * v;
        res[h] = __expf(t);
    }

    int p = d_offsets[d] + atomicAdd(&d_count2[d], 1);
    __half2 h01 = __floats2half2_rn(res[0], res[1]);
    __half2 h23 = __floats2half2_rn(res[2], res[3]);
    d_pay[p] = make_uint4(*(uint32_t*)&h01, *(uint32_t*)&h23,
                          (uint32_t)s, 0u);
}

// ---------------- K7: warp-per-node softmax + DUAL-STREAM aggregate --------
__global__ void k_aggregate(float* __restrict__ out) {
    int warp = (blockIdx.x * blockDim.x + threadIdx.x) >> 5;
    int lane = threadIdx.x & 31;
    if (warp >= N_NODES) return;
    int n = warp;

    int begin = d_offsets[n];
    int deg = d_offsets[n + 1] - begin;
    if (deg == 0) return;

    int hl = lane >> 3;
    float s0 = 0.f, s1 = 0.f, s2 = 0.f, s3 = 0.f;
    float acc0 = 0.f, acc1 = 0.f, acc2 = 0.f, acc3 = 0.f;
    float bcc0 = 0.f, bcc1 = 0.f, bcc2 = 0.f, bcc3 = 0.f;

    for (int b = 0; b < deg; b += 32) {
        int j = b + lane;
        uint4 pv = make_uint4(0u, 0u, 0u, 0u);
        if (j < deg) pv = d_pay[begin + j];
        int sn = (int)pv.z;

        float2 f01 = __half22float2(*(__half2*)&pv.x);
        float2 f23 = __half22float2(*(__half2*)&pv.y);
        s0 += f01.x; s1 += f01.y; s2 += f23.x; s3 += f23.y;

        int cnt = min(32, deg - b);
        int half = cnt >> 1;
        // two independent dependency streams: edges k and k+half
        #pragma unroll 2
        for (int k = 0; k < half; k++) {
            // stream A
            uint32_t pxa = __shfl_sync(0xffffffffu, pv.x, k);
            uint32_t pya = __shfl_sync(0xffffffffu, pv.y, k);
            int sna = __shfl_sync(0xffffffffu, sn, k);
            // stream B
            uint32_t pxb = __shfl_sync(0xffffffffu, pv.x, k + half);
            uint32_t pyb = __shfl_sync(0xffffffffu, pv.y, k + half);
            int snb = __shfl_sync(0xffffffffu, sn, k + half);

            uint32_t sela = (hl < 2) ? pxa : pya;
            uint32_t selb = (hl < 2) ? pxb : pyb;
            float2 wfa = __half22float2(*(__half2*)&sela);
            float2 wfb = __half22float2(*(__half2*)&selb);
            float wa = (hl & 1) ? wfa.y : wfa.x;
            float wb = (hl & 1) ? wfb.y : wfb.x;

            uint2 hva = *(const uint2*)(d_feat_h + (size_t)sna * 128 + lane * 4);
            uint2 hvb = *(const uint2*)(d_feat_h + (size_t)snb * 128 + lane * 4);

            float2 a0 = __half22float2(*(__half2*)&hva.x);
            float2 a1 = __half22float2(*(__half2*)&hva.y);
            float2 b0 = __half22float2(*(__half2*)&hvb.x);
            float2 b1 = __half22float2(*(__half2*)&hvb.y);

            acc0 += a0.x * wa; acc1 += a0.y * wa;
            acc2 += a1.x * wa; acc3 += a1.y * wa;
            bcc0 += b0.x * wb; bcc1 += b0.y * wb;
            bcc2 += b1.x * wb; bcc3 += b1.y * wb;
        }
        if (cnt & 1) {
            int k = cnt - 1;
            uint32_t px = __shfl_sync(0xffffffffu, pv.x, k);
            uint32_t py = __shfl_sync(0xffffffffu, pv.y, k);
            int snk = __shfl_sync(0xffffffffu, sn, k);
            uint32_t sel = (hl < 2) ? px : py;
            float2 wf = __half22float2(*(__half2*)&sel);
            float w = (hl & 1) ? wf.y : wf.x;
            uint2 hv = *(const uint2*)(d_feat_h + (size_t)snk * 128 + lane * 4);
            float2 f0 = __half22float2(*(__half2*)&hv.x);
            float2 f1 = __half22float2(*(__half2*)&hv.y);
            acc0 += f0.x * w; acc1 += f0.y * w;
            acc2 += f1.x * w; acc3 += f1.y * w;
        }
    }
    acc0 += bcc0; acc1 += bcc1; acc2 += bcc2; acc3 += bcc3;

    #pragma unroll
    for (int o = 16; o > 0; o >>= 1) {
        s0 += __shfl_xor_sync(0xffffffffu, s0, o);
        s1 += __shfl_xor_sync(0xffffffffu, s1, o);
        s2 += __shfl_xor_sync(0xffffffffu, s2, o);
        s3 += __shfl_xor_sync(0xffffffffu, s3, o);
    }
    float s = (hl < 2) ? (hl == 0 ? s0 : s1) : (hl == 2 ? s2 : s3);
    float inv = 1.f / s;

    float4* op = (float4*)(out + (size_t)n * 128 + lane * 4);
    float4 ov = *op;  // residual + bias from GEMM epilogue
    ov.x += acc0 * inv; ov.y += acc1 * inv;
    ov.z += acc2 * inv; ov.w += acc3 * inv;
    *op = ov;
}

// ---------------------------------------------------------------------------
extern "C" void kernel_launch(void* const* d_in, const int* in_sizes, int n_in,
                              void* d_out, int out_size) {
    const float* node_inputs = (const float*)d_in[0];
    const float* edge_inputs = (const float*)d_in[1];
    const int*   src         = (const int*)d_in[2];
    const int*   dst         = (const int*)d_in[3];
    const float* W_fc        = (const float*)d_in[4];
    const float* attn_src_p  = (const float*)d_in[5];
    const float* attn_dst_p  = (const float*)d_in[6];
    const float* W_edge      = (const float*)d_in[7];
    const float* attn_edge_p = (const float*)d_in[8];
    const float* W_res       = (const float*)d_in[9];
    const float* bias_p      = (const float*)d_in[10];
    float* out = (float*)d_out;

    static cudaStream_t s1;
    static cudaEvent_t evA, evS;
    static bool inited = false;
    if (!inited) {
        cudaStreamCreateWithFlags(&s1, cudaStreamNonBlocking);
        cudaEventCreateWithFlags(&evA, cudaEventDisableTiming);
        cudaEventCreateWithFlags(&evS, cudaEventDisableTiming);
        cudaFuncSetAttribute(k_gemm_bf,
                             cudaFuncAttributeMaxDynamicSharedMemorySize,
                             GEMM_SMEM);
        inited = true;
    }

    // setup on default stream
    k_setup<<<128, 256>>>(W_fc, W_res, W_edge, attn_edge_p);
    cudaEventRecord(evA, 0);

    // side stream: histogram + scan (independent of GEMM)
    cudaStreamWaitEvent(s1, evA, 0);
    k_hist<<<(N_EDGES / 4 + 255) / 256, 256, 0, s1>>>(dst);
    k_scan_mb<<<SCAN_BLOCKS, 1024, 0, s1>>>();
    cudaEventRecord(evS, s1);

    // main stream: GEMM overlapping with hist/scan
    k_gemm_bf<<<GEMM_GRID, 512, GEMM_SMEM>>>(
        node_inputs, out, bias_p, attn_src_p, attn_dst_p, N_NODES);

    // join, then edge + aggregate
    cudaStreamWaitEvent(0, evS, 0);
    k_edge_e<<<(N_EDGES + 255) / 256, 256>>>(edge_inputs, src, dst);
    k_aggregate<<<(N_NODES * 32 + 255) / 256, 256>>>(out);
}